// round 14
// baseline (speedup 1.0000x reference)
#include <cuda_runtime.h>
#include <cstdint>

#define P_GAIN     2.0f
#define P_BASELINE 100.0f
static constexpr int B = 32;
static constexpr int E = 64;
static constexpr int H = 128;
static constexpr int W = 128;
static constexpr int R = 13;
static constexpr int D = 32;
static constexpr int HALF = R / 2;
static constexpr int PIX = H * W;               // 16384
static constexpr int NPX = R * R;               // 169
static constexpr int BAND = 8;
static constexpr int NBAND = H / BAND;          // 16
static constexpr int BAND_F4 = BAND * W / 4;    // 256
static constexpr int BAND_BYTES = BAND * W * 4; // 4096
static constexpr int ESPLIT = 4;
static constexpr int EPB = E / ESPLIT;          // 16
static constexpr int NSTAGE = 4;
static constexpr int PTASKS = BAND * R;         // 104 patch pixels per band

__device__ __forceinline__ uint64_t evict_first_policy() {
    uint64_t pol;
    asm("createpolicy.fractional.L2::evict_first.b64 %0, 1.0;" : "=l"(pol));
    return pol;
}
__device__ __forceinline__ uint32_t smem_u32(const void* p) {
    uint32_t a;
    asm("{ .reg .u64 tmp; cvta.to.shared.u64 tmp, %1; cvt.u32.u64 %0, tmp; }"
        : "=r"(a) : "l"(p));
    return a;
}
__device__ __forceinline__ void bulk_store(float* dst, uint32_t src,
                                           unsigned bytes, uint64_t pol) {
    asm volatile(
        "cp.async.bulk.global.shared::cta.bulk_group.L2::cache_hint "
        "[%0], [%1], %2, %3;"
        :: "l"(dst), "r"(src), "r"(bytes), "l"(pol) : "memory");
}

// ---------------------------------------------------------------------------
// SINGLE kernel: one block per (band, frame, emitter-split). No patch
// prepass, no scratch globals, no handshake.
//   misses (~84%): scaled bg band leaves via TMA bulk store + L2::evict_first
//     (distributed issuers), exactly the proven R11 path.
//   hits: the needed band-rows of the PSF patch are evaluated IN-BLOCK with a
//     coalesced 16-lane cooperative dot: for patch pixel p, its 64 coeffs are
//     one contiguous 256B run; lane k4 of a 16-lane group loads float4 #k4,
//     computes (f.x + f.y*px1 + f.z*px2 + f.w*px3) * pz[a]*py[b], and a
//     4-step shfl_xor tree reduces the group. Then band+patch is composed in
//     a staging ring and bulk-stored like the misses.
// JAX .at[].add(mode='drop') semantics: negative scatter targets wrap
// (+H / +W); targets >= H/W are dropped.
// ---------------------------------------------------------------------------
__global__ __launch_bounds__(256, 6) void render_kernel(const float* __restrict__ xyz,
                                                        const float* __restrict__ nph,
                                                        const float* __restrict__ bg,
                                                        const float* __restrict__ coeff,
                                                        float* __restrict__ out)
{
    const int band  = blockIdx.x;            // 0..NBAND-1
    const int frame = blockIdx.y;            // 0..B-1
    const int esp   = blockIdx.z;            // 0..ESPLIT-1
    const int bs    = band * BAND;
    const int t     = threadIdx.x;

    __shared__ float4 s_bg[BAND_F4];             // 4 KB scaled bg band
    __shared__ float4 s_st[NSTAGE][BAND_F4];     // 16 KB staging ring
    __shared__ float  s_patch[BAND][16];         // current hit's patch rows
    __shared__ int    s_r0[EPB];
    __shared__ int    s_c0[EPB];
    __shared__ unsigned char s_hit[EPB];
    __shared__ int    s_hlist[EPB];
    __shared__ int    s_nhit;

    if (t == 0) s_nhit = 0;

    const uint64_t pol = evict_first_policy();
    const size_t out_base = ((size_t)frame * E + esp * EPB) * PIX + (size_t)bs * W;

    // ---- load + scale bg band ----
    {
        const float4 b4 = reinterpret_cast<const float4*>(
            bg + (size_t)frame * PIX + (size_t)bs * W)[t];
        float4 v;
        v.x = fmaf(b4.x, P_GAIN, P_BASELINE);
        v.y = fmaf(b4.y, P_GAIN, P_BASELINE);
        v.z = fmaf(b4.z, P_GAIN, P_BASELINE);
        v.w = fmaf(b4.w, P_GAIN, P_BASELINE);
        s_bg[t] = v;
    }
    __syncthreads();

    // ---- classify this split's 16 emitters ----
    if (t < EPB) {
        const int ge = frame * E + esp * EPB + t;
        const float x = xyz[ge * 3 + 0];
        const float y = xyz[ge * 3 + 1];
        const int r0 = (int)floorf(y) - HALF;
        s_r0[t] = r0;
        s_c0[t] = (int)floorf(x) - HALF;
        int hit = 0;
        #pragma unroll
        for (int lr = 0; lr < BAND; ++lr) {
            int rr = bs + lr - r0;
            if (rr >= H) rr -= H;            // wrapped negative target row
            if ((unsigned)rr < (unsigned)R) hit = 1;
        }
        s_hit[t] = (unsigned char)hit;
        if (hit) s_hlist[atomicAdd(&s_nhit, 1)] = t;
    }
    __syncthreads();

    // ---- miss emitters: distributed bulk stores from s_bg ----
    const bool issuer = (t < EPB) && !s_hit[t];
    if (issuer) {
        asm volatile("fence.proxy.async.shared::cta;" ::: "memory");
        bulk_store(out + out_base + (size_t)t * PIX, smem_u32(s_bg),
                   (unsigned)BAND_BYTES, pol);
        asm volatile("cp.async.bulk.commit_group;" ::: "memory");
    }

    // ---- hit emitters: in-block patch eval + compose + bulk store ----
    const float4 base_v = s_bg[t];
    const int pixi = t * 4;
    const int lrc  = pixi >> 7;              // compose local row (W==128)
    const int colc = pixi & (W - 1);
    const int nhit = s_nhit;

    const int sub = t & 15;                  // k4 lane within 16-group
    const int pg  = t >> 4;                  // pixel-group id (0..15)

    #pragma unroll 1
    for (int kk = 0; kk < nhit; ++kk) {
        const int em = s_hlist[kk];
        const int ge = frame * E + esp * EPB + em;
        const int r0 = s_r0[em];
        const int c0 = s_c0[em];
        const int sb = kk & (NSTAGE - 1);

        if (kk >= NSTAGE) {                  // staging reuse: drain reads
            if (t == 0)
                asm volatile("cp.async.bulk.wait_group.read 0;" ::: "memory");
            __syncthreads();
        }

        // emitter scalars (broadcast loads, L1-hot)
        const float x  = xyz[ge * 3 + 0];
        const float y  = xyz[ge * 3 + 1];
        const float zv = xyz[ge * 3 + 2];
        const float dx = x - floorf(x);
        const float dy = y - floorf(y);
        float zc = fminf(fmaxf(zv, 0.0f), (float)(D - 1) - 1e-6f);
        const float zf = floorf(zc);
        const int   zi = (int)zf;
        const float dz = zc - zf;
        const float amp = nph[ge] * P_GAIN;

        const float px1 = dx, px2 = dx * dx, px3 = px2 * dx;
        float pyv[4], pzv[4];
        pyv[0] = 1.0f; pyv[1] = dy; pyv[2] = dy * dy; pyv[3] = pyv[2] * dy;
        pzv[0] = 1.0f; pzv[1] = dz; pzv[2] = dz * dz; pzv[3] = pzv[2] * dz;
        const float wzy = pzv[sub >> 2] * pyv[sub & 3];

        // cooperative coalesced patch eval: 16 lanes per pixel
        #pragma unroll 1
        for (int p = pg; p < PTASKS; p += 16) {
            const int lr = p / R;
            const int cx = p - lr * R;
            int rr = bs + lr - r0;
            if (rr >= H) rr -= H;            // wrapped negative target row
            float partial = 0.0f;
            if ((unsigned)rr < (unsigned)R) {
                const float4 f = *reinterpret_cast<const float4*>(
                    coeff + (((size_t)zi * NPX) + rr * R + cx) * 64 + sub * 4);
                float sc = f.x;
                sc = fmaf(f.y, px1, sc);
                sc = fmaf(f.z, px2, sc);
                sc = fmaf(f.w, px3, sc);
                partial = sc * wzy;
            }
            partial += __shfl_xor_sync(0xffffffffu, partial, 8);
            partial += __shfl_xor_sync(0xffffffffu, partial, 4);
            partial += __shfl_xor_sync(0xffffffffu, partial, 2);
            partial += __shfl_xor_sync(0xffffffffu, partial, 1);
            if (sub == 0) s_patch[lr][cx] = partial * amp;
        }
        __syncthreads();

        // compose band + patch into staging
        float4 v = base_v;
        int rr = bs + lrc - r0;
        if (rr >= H) rr -= H;                // wrapped negative target row
        if ((unsigned)rr < (unsigned)R) {
            float* vp = &v.x;
            #pragma unroll
            for (int j = 0; j < 4; ++j) {
                int cj = colc - c0 + j;
                if (cj >= W) cj -= W;        // wrapped negative target col
                if ((unsigned)cj < (unsigned)R) vp[j] += s_patch[lrc][cj];
            }
        }
        s_st[sb][t] = v;
        __syncthreads();

        if (t == 0) {
            asm volatile("fence.proxy.async.shared::cta;" ::: "memory");
            bulk_store(out + out_base + (size_t)em * PIX, smem_u32(s_st[sb]),
                       (unsigned)BAND_BYTES, pol);
            asm volatile("cp.async.bulk.commit_group;" ::: "memory");
        }
    }

    // ---- drain all pending bulk reads before smem is released ----
    if (issuer || t == 0) {
        asm volatile("cp.async.bulk.wait_group.read 0;" ::: "memory");
    }
    __syncthreads();
}

// ---------------------------------------------------------------------------
// Launch: ONE kernel. Inputs identified by element count:
//   xyz [B,E,3]=6144, n_photons [B,E]=2048, bg [B,H,W]=524288,
//   coeff [D,R,R,4,4,4]=346112.  Output: [B,E,H,W] f32.
// ---------------------------------------------------------------------------
extern "C" void kernel_launch(void* const* d_in, const int* in_sizes, int n_in,
                              void* d_out, int out_size)
{
    const float* xyz   = nullptr;
    const float* nph   = nullptr;
    const float* bg    = nullptr;
    const float* coeff = nullptr;
    for (int i = 0; i < n_in; ++i) {
        switch (in_sizes[i]) {
            case B * E * 3:      xyz   = (const float*)d_in[i]; break;
            case B * E:          nph   = (const float*)d_in[i]; break;
            case B * H * W:      bg    = (const float*)d_in[i]; break;
            case D * R * R * 64: coeff = (const float*)d_in[i]; break;
        }
    }
    float* out = (float*)d_out;

    dim3 grid(NBAND, B, ESPLIT);
    render_kernel<<<grid, 256>>>(xyz, nph, bg, coeff, out);
}

// round 15
// speedup vs baseline: 1.4292x; 1.4292x over previous
#include <cuda_runtime.h>
#include <cstdint>

#define P_GAIN     2.0f
#define P_BASELINE 100.0f
static constexpr int B = 32;
static constexpr int E = 64;
static constexpr int H = 128;
static constexpr int W = 128;
static constexpr int R = 13;
static constexpr int D = 32;
static constexpr int HALF = R / 2;
static constexpr int PIX = H * W;               // 16384
static constexpr int NPX = R * R;               // 169
static constexpr int PPAD = 176;
static constexpr int BAND = 8;
static constexpr int NBAND = H / BAND;          // 16
static constexpr int BAND_F4 = BAND * W / 4;    // 256
static constexpr int BAND_BYTES = BAND * W * 4; // 4096
static constexpr int ESPLIT = 4;
static constexpr int EPB = E / ESPLIT;          // 16
static constexpr int NSTAGE = 4;

// Scratch (static device global — no allocation)
__device__ float g_patch[B * E * PPAD];         // 1.44 MB pre-scaled patches

__device__ __forceinline__ uint64_t evict_first_policy() {
    uint64_t pol;
    asm("createpolicy.fractional.L2::evict_first.b64 %0, 1.0;" : "=l"(pol));
    return pol;
}
__device__ __forceinline__ uint32_t smem_u32(const void* p) {
    uint32_t a;
    asm("{ .reg .u64 tmp; cvta.to.shared.u64 tmp, %1; cvt.u32.u64 %0, tmp; }"
        : "=r"(a) : "l"(p));
    return a;
}
__device__ __forceinline__ void bulk_store(float* dst, uint32_t src,
                                           unsigned bytes, uint64_t pol) {
    asm volatile(
        "cp.async.bulk.global.shared::cta.bulk_group.L2::cache_hint "
        "[%0], [%1], %2, %3;"
        :: "l"(dst), "r"(src), "r"(bytes), "l"(pol) : "memory");
}

// ---------------------------------------------------------------------------
// Kernel 1: patch precompute, ONE BLOCK PER EMITTER (2048 blocks — full-chip
// parallel, 1-2 waves). 256 threads = 16 pixel-groups x 16 lanes. For patch
// pixel p, its 64 coeffs are one contiguous 256B run; lane `sub` loads float4
// #sub (4 cache lines per warp-load — fully coalesced), evaluates its
// x-polynomial times pz[a]*py[b], and a 4-step shfl_xor tree reduces the
// 16-lane group. No smem, no lists, no barriers.
// ---------------------------------------------------------------------------
__global__ __launch_bounds__(256) void patch_kernel(const float* __restrict__ xyz,
                                                    const float* __restrict__ nph,
                                                    const float* __restrict__ coeff)
{
    const int ge  = blockIdx.x;              // 0 .. B*E-1
    const int t   = threadIdx.x;
    const int sub = t & 15;                  // float4 index within the 64-run
    const int pg  = t >> 4;                  // pixel-group id (0..15)

    // emitter scalars (broadcast loads)
    const float x  = xyz[ge * 3 + 0];
    const float y  = xyz[ge * 3 + 1];
    const float zv = xyz[ge * 3 + 2];
    const float dx = x - floorf(x);
    const float dy = y - floorf(y);
    float zc = fminf(fmaxf(zv, 0.0f), (float)(D - 1) - 1e-6f);
    const float zf = floorf(zc);
    const int   zi = (int)zf;
    const float dz = zc - zf;
    const float amp = nph[ge] * P_GAIN;

    const float px1 = dx, px2 = dx * dx, px3 = px2 * dx;
    float pyv[4], pzv[4];
    pyv[0] = 1.0f; pyv[1] = dy; pyv[2] = dy * dy; pyv[3] = pyv[2] * dy;
    pzv[0] = 1.0f; pzv[1] = dz; pzv[2] = dz * dz; pzv[3] = pzv[2] * dz;
    const float wzy = pzv[sub >> 2] * pyv[sub & 3];   // sub = a*4 + b (z,y)

    const float4* __restrict__ cbase = reinterpret_cast<const float4*>(
        coeff + (size_t)zi * NPX * 64) + sub;

    #pragma unroll
    for (int rnd = 0; rnd < 11; ++rnd) {     // ceil(169/16)
        const int p = rnd * 16 + pg;
        float partial = 0.0f;
        if (p < NPX) {
            const float4 f = cbase[p * 16];
            float sc = f.x;
            sc = fmaf(f.y, px1, sc);
            sc = fmaf(f.z, px2, sc);
            sc = fmaf(f.w, px3, sc);
            partial = sc * wzy;
        }
        partial += __shfl_xor_sync(0xffffffffu, partial, 8);
        partial += __shfl_xor_sync(0xffffffffu, partial, 4);
        partial += __shfl_xor_sync(0xffffffffu, partial, 2);
        partial += __shfl_xor_sync(0xffffffffu, partial, 1);
        if (sub == 0 && p < NPX)
            g_patch[(size_t)ge * PPAD + p] = partial * amp;
    }
}

// ---------------------------------------------------------------------------
// Kernel 2: render — byte-identical to the proven R11 body.
// Block = (band, frame, emitter-split): 16 emitters, 8 rows. Miss emitters:
// scaled bg band via TMA bulk store + L2::evict_first (distributed issuers).
// Hit emitters: compose band+patch in a staging ring, bulk store.
// JAX semantics: negative scatter targets wrap (+H/+W), >= H/W dropped.
// ---------------------------------------------------------------------------
__global__ __launch_bounds__(256) void render_kernel(const float* __restrict__ xyz,
                                                     const float* __restrict__ bg,
                                                     float* __restrict__ out)
{
    const int band  = blockIdx.x;            // 0..NBAND-1
    const int frame = blockIdx.y;            // 0..B-1
    const int esp   = blockIdx.z;            // 0..ESPLIT-1
    const int bs    = band * BAND;
    const int t     = threadIdx.x;

    __shared__ float4 s_bg[BAND_F4];                 // 4 KB scaled bg band
    __shared__ float4 s_st[NSTAGE][BAND_F4];         // 16 KB staging ring
    __shared__ int    s_r0[EPB];
    __shared__ int    s_c0[EPB];
    __shared__ unsigned char s_hit[EPB];
    __shared__ int    s_list[EPB];
    __shared__ int    s_nhit;

    if (t == 0) s_nhit = 0;

    const uint64_t pol = evict_first_policy();
    const size_t out_base = ((size_t)frame * E + esp * EPB) * PIX + (size_t)bs * W;

    // ---- load + scale bg band ----
    {
        const float4 b4 = reinterpret_cast<const float4*>(
            bg + (size_t)frame * PIX + (size_t)bs * W)[t];
        float4 v;
        v.x = fmaf(b4.x, P_GAIN, P_BASELINE);
        v.y = fmaf(b4.y, P_GAIN, P_BASELINE);
        v.z = fmaf(b4.z, P_GAIN, P_BASELINE);
        v.w = fmaf(b4.w, P_GAIN, P_BASELINE);
        s_bg[t] = v;
    }
    __syncthreads();

    // ---- classify this split's 16 emitters ----
    if (t < EPB) {
        const int ge = frame * E + esp * EPB + t;
        const float x = xyz[ge * 3 + 0];
        const float y = xyz[ge * 3 + 1];
        const int r0 = (int)floorf(y) - HALF;
        s_r0[t] = r0;
        s_c0[t] = (int)floorf(x) - HALF;
        int hit = 0;
        #pragma unroll
        for (int lr = 0; lr < BAND; ++lr) {
            int rr = bs + lr - r0;
            if (rr >= H) rr -= H;            // wrapped negative target row
            if ((unsigned)rr < (unsigned)R) hit = 1;
        }
        s_hit[t] = (unsigned char)hit;
        if (hit) s_list[atomicAdd(&s_nhit, 1)] = t;
    }
    __syncthreads();

    // ---- miss emitters: distributed bulk stores from s_bg ----
    const bool issuer = (t < EPB) && !s_hit[t];
    if (issuer) {
        asm volatile("fence.proxy.async.shared::cta;" ::: "memory");
        bulk_store(out + out_base + (size_t)t * PIX, smem_u32(s_bg),
                   (unsigned)BAND_BYTES, pol);
        asm volatile("cp.async.bulk.commit_group;" ::: "memory");
    }

    // ---- hit emitters: compose in staging smem, bulk store ----
    const float4 base_v = s_bg[t];
    const int pix = t * 4;
    const int lr  = pix >> 7;                // local row (W == 128), warp-uniform
    const int col = pix & (W - 1);
    const int nhit = s_nhit;

    #pragma unroll 1
    for (int kk = 0; kk < nhit; ++kk) {
        const int em = s_list[kk];
        const int ge = frame * E + esp * EPB + em;
        const int r0 = s_r0[em];
        const int c0 = s_c0[em];
        const int sb = kk & (NSTAGE - 1);

        if (kk >= NSTAGE) {                  // staging buffer reuse: drain
            if (t == 0)
                asm volatile("cp.async.bulk.wait_group.read 0;" ::: "memory");
            __syncthreads();
        }

        float4 v = base_v;
        int rr = bs + lr - r0;
        if (rr >= H) rr -= H;                // wrapped negative target row
        if ((unsigned)rr < (unsigned)R) {
            const float* __restrict__ pp = g_patch + (size_t)ge * PPAD + rr * R;
            float* vp = &v.x;
            #pragma unroll
            for (int j = 0; j < 4; ++j) {
                int cj = col - c0 + j;
                if (cj >= W) cj -= W;        // wrapped negative target col
                if ((unsigned)cj < (unsigned)R) vp[j] += pp[cj];
            }
        }
        s_st[sb][t] = v;
        __syncthreads();

        if (t == 0) {
            asm volatile("fence.proxy.async.shared::cta;" ::: "memory");
            bulk_store(out + out_base + (size_t)em * PIX, smem_u32(s_st[sb]),
                       (unsigned)BAND_BYTES, pol);
            asm volatile("cp.async.bulk.commit_group;" ::: "memory");
        }
    }

    // ---- drain: every thread with pending groups waits for reads ----
    if (issuer || t == 0) {
        asm volatile("cp.async.bulk.wait_group.read 0;" ::: "memory");
    }
    __syncthreads();   // smem lifetime: no thread exits while TMA may read
}

// ---------------------------------------------------------------------------
// Launch. Inputs identified by element count:
//   xyz [B,E,3]=6144, n_photons [B,E]=2048, bg [B,H,W]=524288,
//   coeff [D,R,R,4,4,4]=346112.  Output: [B,E,H,W] f32.
// ---------------------------------------------------------------------------
extern "C" void kernel_launch(void* const* d_in, const int* in_sizes, int n_in,
                              void* d_out, int out_size)
{
    const float* xyz   = nullptr;
    const float* nph   = nullptr;
    const float* bg    = nullptr;
    const float* coeff = nullptr;
    for (int i = 0; i < n_in; ++i) {
        switch (in_sizes[i]) {
            case B * E * 3:      xyz   = (const float*)d_in[i]; break;
            case B * E:          nph   = (const float*)d_in[i]; break;
            case B * H * W:      bg    = (const float*)d_in[i]; break;
            case D * R * R * 64: coeff = (const float*)d_in[i]; break;
        }
    }
    float* out = (float*)d_out;

    patch_kernel<<<B * E, 256>>>(xyz, nph, coeff);

    dim3 rgrid(NBAND, B, ESPLIT);
    render_kernel<<<rgrid, 256>>>(xyz, bg, out);
}